// round 2
// baseline (speedup 1.0000x reference)
#include <cuda_runtime.h>
#include <cstdint>
#include <cstddef>

#define NN 32768
#define EE 262144

static const size_t O_OUT_V = (size_t)NN * 64;    // out_v starts after out_s
static const size_t O_SC_S  = (size_t)NN * 256;   // after out_s + out_v
static const size_t O_SC_V  = (size_t)NN * 320;   // after sc_s

// ---------------- device scratch (static, no allocation) ----------------
__device__ float g_xs[(size_t)NN * 64];      // x_s @ W_self_s / 8
__device__ float g_xv[(size_t)NN * 192];     // [n][c][i] mixed vectors
__device__ float g_tpw[(size_t)EE * 320];    // MLP output per edge
__device__ int   g_cnt[NN];
__device__ int   g_off[NN + 1];
__device__ int   g_woff[NN];
__device__ int   g_eord[EE];

// ---------------- helpers ----------------
__device__ __forceinline__ unsigned long long pk2(float lo, float hi) {
    unsigned long long r;
    asm("mov.b64 %0, {%1, %2};" : "=l"(r) : "f"(lo), "f"(hi));
    return r;
}
__device__ __forceinline__ void upk2(unsigned long long v, float& lo, float& hi) {
    asm("mov.b64 {%0, %1}, %2;" : "=f"(lo), "=f"(hi) : "l"(v));
}
__device__ __forceinline__ unsigned long long ff2(unsigned long long a,
                                                  unsigned long long b,
                                                  unsigned long long c) {
    unsigned long long d;
    asm("fma.rn.f32x2 %0, %1, %2, %3;" : "=l"(d) : "l"(a), "l"(b), "l"(c));
    return d;
}
__device__ __forceinline__ float silu_f(float x) {
    return x * __fdividef(1.0f, 1.0f + __expf(-x));
}

// ============================================================================
// K1: per-node — sc_s, sc_v (via per-(c,d) attr-mixed weight), self-mix x_s/x_v
// grid 2048 x 256 threads; 16 nodes/block; thread = (d = t&63, jg = t>>6),
// each thread owns 4 nodes.
// ============================================================================
__global__ __launch_bounds__(256) void k_node(
    const float* __restrict__ attr, const float* __restrict__ xs_in,
    const float* __restrict__ xv_in,
    const float* __restrict__ Wscs, const float* __restrict__ Wscv,
    const float* __restrict__ Wss,  const float* __restrict__ Wsv,
    float* __restrict__ out)
{
    __shared__ float sxs[16 * 64];
    __shared__ float sxv[16 * 192];
    __shared__ float sattr[16 * 10];
    const int t = threadIdx.x;
    const int n0 = blockIdx.x * 16;

    for (int i = t; i < 16 * 64;  i += 256) sxs[i]  = xs_in[(size_t)n0 * 64 + i];
    for (int i = t; i < 16 * 192; i += 256) sxv[i]  = xv_in[(size_t)n0 * 192 + i];
    for (int i = t; i < 16 * 10;  i += 256) sattr[i] = attr[(size_t)n0 * 10 + i];
    __syncthreads();

    const int d = t & 63, jg = t >> 6;

    float attrR[4][10];
#pragma unroll
    for (int jj = 0; jj < 4; jj++)
#pragma unroll
        for (int a = 0; a < 10; a++)
            attrR[jj][a] = sattr[(jg * 4 + jj) * 10 + a];

    float accS[4]  = {0.f, 0.f, 0.f, 0.f};
    float accS2[4] = {0.f, 0.f, 0.f, 0.f};
    float accV[4][3]  = {{0.f,0.f,0.f},{0.f,0.f,0.f},{0.f,0.f,0.f},{0.f,0.f,0.f}};
    float accV2[4][3] = {{0.f,0.f,0.f},{0.f,0.f,0.f},{0.f,0.f,0.f},{0.f,0.f,0.f}};

    for (int c = 0; c < 64; c++) {
        float xsc[4], xvc[4][3];
#pragma unroll
        for (int jj = 0; jj < 4; jj++) {
            const int l = jg * 4 + jj;
            xsc[jj] = sxs[l * 64 + c];
            xvc[jj][0] = sxv[(l * 64 + c) * 3 + 0];
            xvc[jj][1] = sxv[(l * 64 + c) * 3 + 1];
            xvc[jj][2] = sxv[(l * 64 + c) * 3 + 2];
        }
        // self-mix
        const float ws2 = __ldg(Wss + c * 64 + d);
        const float wv2 = __ldg(Wsv + c * 64 + d);
#pragma unroll
        for (int jj = 0; jj < 4; jj++) {
            accS2[jj] = fmaf(xsc[jj], ws2, accS2[jj]);
#pragma unroll
            for (int i = 0; i < 3; i++)
                accV2[jj][i] = fmaf(xvc[jj][i], wv2, accV2[jj][i]);
        }
        // attr-mixed weights
        float Ms[4] = {0.f, 0.f, 0.f, 0.f};
        float Mv[4] = {0.f, 0.f, 0.f, 0.f};
#pragma unroll
        for (int a = 0; a < 10; a++) {
            const float ws = __ldg(Wscs + (c * 10 + a) * 64 + d);
            const float wv = __ldg(Wscv + (c * 10 + a) * 64 + d);
#pragma unroll
            for (int jj = 0; jj < 4; jj++) {
                Ms[jj] = fmaf(attrR[jj][a], ws, Ms[jj]);
                Mv[jj] = fmaf(attrR[jj][a], wv, Mv[jj]);
            }
        }
#pragma unroll
        for (int jj = 0; jj < 4; jj++) {
            accS[jj] = fmaf(xsc[jj], Ms[jj], accS[jj]);
#pragma unroll
            for (int i = 0; i < 3; i++)
                accV[jj][i] = fmaf(xvc[jj][i], Mv[jj], accV[jj][i]);
        }
    }

    const float S640 = 0.039528470752104741f;  // 1/sqrt(640)
#pragma unroll
    for (int jj = 0; jj < 4; jj++) {
        const int n = n0 + jg * 4 + jj;
        out[O_SC_S + (size_t)n * 64 + d] = accS[jj] * S640;
#pragma unroll
        for (int i = 0; i < 3; i++)
            out[O_SC_V + (size_t)n * 192 + d * 3 + i] = accV[jj][i] * S640;
        g_xs[(size_t)n * 64 + d] = accS2[jj] * 0.125f;
#pragma unroll
        for (int i = 0; i < 3; i++)
            g_xv[(size_t)n * 192 + d * 3 + i] = accV2[jj][i] * 0.125f;
    }
}

// ============================================================================
// K2: edge MLP, thread-per-edge, all weights in smem, f32x2 packed FMA.
// grid 1024 x 256; dynamic smem = (29184 weights + 256*65 h-staging) floats.
// ============================================================================
__global__ __launch_bounds__(256, 1) void k_mlp(
    const float* __restrict__ feats,
    const float* __restrict__ W0, const float* __restrict__ W1,
    const float* __restrict__ W2, const float* __restrict__ W3)
{
    extern __shared__ float sw[];
    float* sW0 = sw;             // 8x64
    float* sW1 = sw + 512;       // 64x64
    float* sW2 = sw + 4608;      // 64x64
    float* sW3 = sw + 8704;      // 64x320
    float* sH  = sw + 29184;     // 256 x 65 (padded)

    const int t = threadIdx.x;
    for (int i = t; i < 512;   i += 256) sW0[i] = W0[i];
    for (int i = t; i < 4096;  i += 256) { sW1[i] = W1[i]; sW2[i] = W2[i]; }
    for (int i = t; i < 20480; i += 256) sW3[i] = W3[i];
    __syncthreads();

    const int e = blockIdx.x * 256 + t;
    float* h = sH + t * 65;

    const float4 fa = *(const float4*)(feats + (size_t)e * 8);
    const float4 fb = *(const float4*)(feats + (size_t)e * 8 + 4);
    const float f[8] = {fa.x, fa.y, fa.z, fa.w, fb.x, fb.y, fb.z, fb.w};

    unsigned long long acc[32];

    // layer 0: (8 -> 64), scale 1/sqrt(8), silu
#pragma unroll
    for (int dp = 0; dp < 32; dp++) acc[dp] = 0ull;
#pragma unroll
    for (int c = 0; c < 8; c++) {
        const unsigned long long a2 = pk2(f[c], f[c]);
        const unsigned long long* w = (const unsigned long long*)(sW0 + c * 64);
#pragma unroll
        for (int dp = 0; dp < 32; dp++) acc[dp] = ff2(a2, w[dp], acc[dp]);
    }
#pragma unroll
    for (int dp = 0; dp < 32; dp++) {
        float lo, hi; upk2(acc[dp], lo, hi);
        h[2 * dp]     = silu_f(lo * 0.3535533905932738f);
        h[2 * dp + 1] = silu_f(hi * 0.3535533905932738f);
    }

    // layers 1, 2: (64 -> 64), scale 1/8, silu
    for (int L = 0; L < 2; L++) {
        const float* W = L ? sW2 : sW1;
#pragma unroll
        for (int dp = 0; dp < 32; dp++) acc[dp] = 0ull;
        for (int c = 0; c < 64; c++) {
            const float hc = h[c];
            const unsigned long long a2 = pk2(hc, hc);
            const unsigned long long* w = (const unsigned long long*)(W + c * 64);
#pragma unroll
            for (int dp = 0; dp < 32; dp++) acc[dp] = ff2(a2, w[dp], acc[dp]);
        }
#pragma unroll
        for (int dp = 0; dp < 32; dp++) {
            float lo, hi; upk2(acc[dp], lo, hi);
            h[2 * dp]     = silu_f(lo * 0.125f);
            h[2 * dp + 1] = silu_f(hi * 0.125f);
        }
    }

    // layer 3: (64 -> 320) in 5 chunks of 64, scale 1/8, write tpw
    float* outp = g_tpw + (size_t)e * 320;
    for (int ch = 0; ch < 5; ch++) {
#pragma unroll
        for (int dp = 0; dp < 32; dp++) acc[dp] = 0ull;
        for (int c = 0; c < 64; c++) {
            const float hc = h[c];
            const unsigned long long a2 = pk2(hc, hc);
            const unsigned long long* w =
                (const unsigned long long*)(sW3 + c * 320 + ch * 64);
#pragma unroll
            for (int dp = 0; dp < 32; dp++) acc[dp] = ff2(a2, w[dp], acc[dp]);
        }
#pragma unroll
        for (int dp = 0; dp < 32; dp++) {
            float lo, hi; upk2(acc[dp], lo, hi);
            *(float2*)(outp + ch * 64 + 2 * dp) =
                make_float2(lo * 0.125f, hi * 0.125f);
        }
    }
}

// ============================================================================
// CSR build (deterministic: per-node segments sorted ascending)
// ============================================================================
__global__ void k_zero() {
    const int i = blockIdx.x * blockDim.x + threadIdx.x;
    if (i < NN) g_cnt[i] = 0;
}
__global__ void k_count(const int* __restrict__ recv) {
    const int e = blockIdx.x * blockDim.x + threadIdx.x;
    if (e < EE) atomicAdd(&g_cnt[recv[e]], 1);
}
__global__ void k_scan() {  // single block, 1024 threads, 32 nodes each
    __shared__ int ss[1024];
    const int t = threadIdx.x;
    const int base = t * 32;
    int loc[32];
    int s = 0;
#pragma unroll
    for (int i = 0; i < 32; i++) { loc[i] = s; s += g_cnt[base + i]; }
    ss[t] = s;
    __syncthreads();
    for (int dd = 1; dd < 1024; dd <<= 1) {
        const int v = (t >= dd) ? ss[t - dd] : 0;
        __syncthreads();
        ss[t] += v;
        __syncthreads();
    }
    const int pre = (t > 0) ? ss[t - 1] : 0;
#pragma unroll
    for (int i = 0; i < 32; i++) {
        g_off[base + i] = pre + loc[i];
        g_woff[base + i] = 0;
    }
    if (t == 1023) g_off[NN] = pre + s;
}
__global__ void k_fill(const int* __restrict__ recv) {
    const int e = blockIdx.x * blockDim.x + threadIdx.x;
    if (e < EE) {
        const int r = recv[e];
        const int p = atomicAdd(&g_woff[r], 1);
        g_eord[g_off[r] + p] = e;
    }
}
__global__ void k_sort() {
    const int n = blockIdx.x * blockDim.x + threadIdx.x;
    if (n >= NN) return;
    const int s = g_off[n], e = g_off[n + 1];
    for (int i = s + 1; i < e; i++) {
        const int v = g_eord[i];
        int j = i - 1;
        while (j >= s && g_eord[j] > v) { g_eord[j + 1] = g_eord[j]; j--; }
        g_eord[j + 1] = v;
    }
}

// ============================================================================
// K4: gather-side message aggregation + fused output GEMMs.
// grid 8192 x 256; 4 nodes/block; 64 threads per node (thread = channel c).
// ============================================================================
__global__ __launch_bounds__(256) void k_agg(
    const int* __restrict__ send, const float* __restrict__ eattr,
    const float* __restrict__ Wms, const float* __restrict__ Wmv,
    float* __restrict__ out)
{
    __shared__ float sms[4][128];
    __shared__ float smv[4][192][3];
    const int t = threadIdx.x;
    const int g = t >> 6, c = t & 63;
    const int n = blockIdx.x * 4 + g;
    const int e0 = g_off[n], e1 = g_off[n + 1];

    float as0 = 0.f, as1 = 0.f;
    float av0[3] = {0.f, 0.f, 0.f};
    float av1[3] = {0.f, 0.f, 0.f};
    float av2[3] = {0.f, 0.f, 0.f};

    for (int p = e0; p < e1; p++) {
        const int e = g_eord[p];
        const int s = __ldg(send + e);
        const float* ea = eattr + (size_t)e * 4;
        const float sh0 = __ldg(ea);
        const float s1x = __ldg(ea + 1), s1y = __ldg(ea + 2), s1z = __ldg(ea + 3);
        const float* tp = g_tpw + (size_t)e * 320 + c;
        const float w0 = tp[0], w1 = tp[64], w2 = tp[128], w3 = tp[192], w4 = tp[256];
        const float xs = __ldg(g_xs + (size_t)s * 64 + c);
        const float* xvp = g_xv + (size_t)s * 192 + c * 3;
        const float xv0 = __ldg(xvp), xv1 = __ldg(xvp + 1), xv2 = __ldg(xvp + 2);

        as0 = fmaf(w0 * xs, sh0, as0);
        const float dt = xv0 * s1x + xv1 * s1y + xv2 * s1z;
        as1 = fmaf(w3, dt, as1);

        const float t1 = w1 * xs;
        av0[0] = fmaf(t1, s1x, av0[0]);
        av0[1] = fmaf(t1, s1y, av0[1]);
        av0[2] = fmaf(t1, s1z, av0[2]);

        av1[0] = fmaf(w2 * xv0, sh0, av1[0]);
        av1[1] = fmaf(w2 * xv1, sh0, av1[1]);
        av1[2] = fmaf(w2 * xv2, sh0, av1[2]);

        const float cx = xv1 * s1z - xv2 * s1y;
        const float cy = xv2 * s1x - xv0 * s1z;
        const float cz = xv0 * s1y - xv1 * s1x;
        av2[0] = fmaf(w4, cx, av2[0]);
        av2[1] = fmaf(w4, cy, av2[1]);
        av2[2] = fmaf(w4, cz, av2[2]);
    }

    const float INV  = 0.3535533905932738f;                 // 1/sqrt(8)
    const float INV3 = INV * 0.5773502691896258f;           // /sqrt(3)
    const float INV2 = INV * 0.7071067811865476f;           // /sqrt(2)
    sms[g][c]      = as0 * INV;
    sms[g][64 + c] = as1 * INV3;
#pragma unroll
    for (int i = 0; i < 3; i++) {
        smv[g][c][i]       = av0[i] * INV;
        smv[g][64 + c][i]  = av1[i] * INV;
        smv[g][128 + c][i] = av2[i] * INV2;
    }
    __syncthreads();

    // output GEMMs, thread d = c
    const int d = c;
    float o = 0.f;
    for (int k = 0; k < 128; k++)
        o = fmaf(sms[g][k], __ldg(Wms + k * 64 + d), o);
    out[(size_t)n * 64 + d] = o * 0.08838834764831845f;     // 1/sqrt(128)

    float ov0 = 0.f, ov1 = 0.f, ov2 = 0.f;
    for (int k = 0; k < 192; k++) {
        const float w = __ldg(Wmv + k * 64 + d);
        ov0 = fmaf(smv[g][k][0], w, ov0);
        ov1 = fmaf(smv[g][k][1], w, ov1);
        ov2 = fmaf(smv[g][k][2], w, ov2);
    }
    const size_t ob = O_OUT_V + (size_t)n * 192 + d * 3;
    const float S192 = 0.07216878364870323f;                // 1/sqrt(192)
    out[ob]     = ov0 * S192;
    out[ob + 1] = ov1 * S192;
    out[ob + 2] = ov2 * S192;
}

// ============================================================================
extern "C" void kernel_launch(void* const* d_in, const int* in_sizes, int n_in,
                              void* d_out, int out_size)
{
    const float* node_attrs = (const float*)d_in[0];
    const float* x_s        = (const float*)d_in[1];
    const float* x_v        = (const float*)d_in[2];
    const float* edge_attrs = (const float*)d_in[3];
    const float* edge_feats = (const float*)d_in[4];
    const int*   senders    = (const int*)d_in[5];
    const int*   receivers  = (const int*)d_in[6];
    const float* W_sc_s     = (const float*)d_in[7];
    const float* W_sc_v     = (const float*)d_in[8];
    const float* W_self_s   = (const float*)d_in[9];
    const float* W_self_v   = (const float*)d_in[10];
    const float* mlp_W0     = (const float*)d_in[11];
    const float* mlp_W1     = (const float*)d_in[12];
    const float* mlp_W2     = (const float*)d_in[13];
    const float* mlp_W3     = (const float*)d_in[14];
    const float* W_msg_s    = (const float*)d_in[15];
    const float* W_msg_v    = (const float*)d_in[16];
    float* out = (float*)d_out;

    const size_t mlp_smem = (size_t)(29184 + 256 * 65) * sizeof(float); // 183296
    cudaFuncSetAttribute(k_mlp, cudaFuncAttributeMaxDynamicSharedMemorySize,
                         (int)mlp_smem);

    k_node<<<NN / 16, 256>>>(node_attrs, x_s, x_v, W_sc_s, W_sc_v,
                             W_self_s, W_self_v, out);
    k_mlp<<<EE / 256, 256, mlp_smem>>>(edge_feats, mlp_W0, mlp_W1, mlp_W2, mlp_W3);
    k_zero<<<NN / 256, 256>>>();
    k_count<<<EE / 256, 256>>>(receivers);
    k_scan<<<1, 1024>>>();
    k_fill<<<EE / 256, 256>>>(receivers);
    k_sort<<<NN / 128, 128>>>();
    k_agg<<<NN / 4, 256>>>(senders, edge_attrs, W_msg_s, W_msg_v, out);
}

// round 3
// speedup vs baseline: 1.0935x; 1.0935x over previous
#include <cuda_runtime.h>
#include <cstdint>
#include <cstddef>

#define NN 32768
#define EE 262144

static const size_t O_OUT_V = (size_t)NN * 64;
static const size_t O_SC_S  = (size_t)NN * 256;
static const size_t O_SC_V  = (size_t)NN * 320;

typedef unsigned long long ull;

// ---------------- device scratch ----------------
__device__ float  g_xs[(size_t)NN * 64];
__device__ float4 g_xv4[(size_t)NN * 64];        // [n][c] -> (x,y,z,0)
__device__ float  g_tpw[(size_t)EE * 320];
__device__ ull    g_wsv[640 * 64];               // packed (W_sc_s, W_sc_v)
__device__ float2 g_wself[64 * 64];              // packed (W_self_s, W_self_v)
__device__ int    g_cnt[NN];
__device__ int    g_off[NN + 1];
__device__ int    g_woff[NN];
__device__ int    g_eord[EE];

// ---------------- helpers ----------------
__device__ __forceinline__ ull pk2(float lo, float hi) {
    ull r; asm("mov.b64 %0, {%1, %2};" : "=l"(r) : "f"(lo), "f"(hi)); return r;
}
__device__ __forceinline__ void upk2(ull v, float& lo, float& hi) {
    asm("mov.b64 {%0, %1}, %2;" : "=f"(lo), "=f"(hi) : "l"(v));
}
__device__ __forceinline__ ull ff2(ull a, ull b, ull c) {
    ull d; asm("fma.rn.f32x2 %0, %1, %2, %3;" : "=l"(d) : "l"(a), "l"(b), "l"(c));
    return d;
}
__device__ __forceinline__ float silu_f(float x) {
    return x * __fdividef(1.0f, 1.0f + __expf(-x));
}

// ============================================================================
// K0: weight interleave prepass
// ============================================================================
__global__ void k_prep(const float* __restrict__ Wscs, const float* __restrict__ Wscv,
                       const float* __restrict__ Wss,  const float* __restrict__ Wsv) {
    const int i = blockIdx.x * 256 + threadIdx.x;
    if (i < 640 * 64) g_wsv[i] = pk2(Wscs[i], Wscv[i]);
    if (i < 64 * 64)  g_wself[i] = make_float2(Wss[i], Wsv[i]);
}

// ============================================================================
// K1: per-node sc_s/sc_v + self-mix, f32x2-packed
// 16 nodes/block, 256 threads; thread = (d, jg), 4 nodes/thread
// ============================================================================
__global__ __launch_bounds__(256) void k_node(
    const float* __restrict__ attr, const float* __restrict__ xs_in,
    const float* __restrict__ xv_in, float* __restrict__ out)
{
    __shared__ float  sxs[16 * 64];
    __shared__ float4 sxv[16 * 64];
    __shared__ float  sattr[16 * 10];
    const int t = threadIdx.x;
    const int n0 = blockIdx.x * 16;

    for (int i = t; i < 16 * 64; i += 256) {
        sxs[i] = xs_in[(size_t)n0 * 64 + i];
        const float* p = xv_in + ((size_t)n0 * 64 + i) * 3;
        sxv[i] = make_float4(p[0], p[1], p[2], 0.f);
    }
    for (int i = t; i < 16 * 10; i += 256) sattr[i] = attr[(size_t)n0 * 10 + i];
    __syncthreads();

    const int d = t & 63, jg = t >> 6;

    ull attrP[4][10];
#pragma unroll
    for (int jj = 0; jj < 4; jj++)
#pragma unroll
        for (int a = 0; a < 10; a++) {
            const float v = sattr[(jg * 4 + jj) * 10 + a];
            attrP[jj][a] = pk2(v, v);
        }

    float accS[4]  = {0.f, 0.f, 0.f, 0.f};
    float accS2[4] = {0.f, 0.f, 0.f, 0.f};
    ull   aV01[4]  = {0ull, 0ull, 0ull, 0ull};
    ull   aV01s[4] = {0ull, 0ull, 0ull, 0ull};
    float aV2[4]   = {0.f, 0.f, 0.f, 0.f};
    float aV2s[4]  = {0.f, 0.f, 0.f, 0.f};

    for (int c = 0; c < 64; c++) {
        const float2 wsf = g_wself[c * 64 + d];
        const ull wvd = pk2(wsf.y, wsf.y);

        float xsr[4], xv2r[4];
        ull xv01r[4];
#pragma unroll
        for (int jj = 0; jj < 4; jj++) {
            const int l = jg * 4 + jj;
            xsr[jj] = sxs[l * 64 + c];
            const float4 xv = sxv[l * 64 + c];
            xv01r[jj] = pk2(xv.x, xv.y);
            xv2r[jj] = xv.z;
            accS2[jj] = fmaf(xsr[jj], wsf.x, accS2[jj]);
            aV01s[jj] = ff2(xv01r[jj], wvd, aV01s[jj]);
            aV2s[jj]  = fmaf(xv2r[jj], wsf.y, aV2s[jj]);
        }

        ull msmv[4] = {0ull, 0ull, 0ull, 0ull};
        const ull* wp = g_wsv + (size_t)c * 640 + d;
#pragma unroll
        for (int a = 0; a < 10; a++) {
            const ull w = __ldg(wp + a * 64);
#pragma unroll
            for (int jj = 0; jj < 4; jj++)
                msmv[jj] = ff2(attrP[jj][a], w, msmv[jj]);
        }
#pragma unroll
        for (int jj = 0; jj < 4; jj++) {
            float Ms, Mv; upk2(msmv[jj], Ms, Mv);
            accS[jj] = fmaf(xsr[jj], Ms, accS[jj]);
            const ull mvd = pk2(Mv, Mv);
            aV01[jj] = ff2(xv01r[jj], mvd, aV01[jj]);
            aV2[jj]  = fmaf(xv2r[jj], Mv, aV2[jj]);
        }
    }

    const float S640 = 0.039528470752104741f;  // 1/sqrt(640)
#pragma unroll
    for (int jj = 0; jj < 4; jj++) {
        const int n = n0 + jg * 4 + jj;
        out[O_SC_S + (size_t)n * 64 + d] = accS[jj] * S640;
        float v0, v1; upk2(aV01[jj], v0, v1);
        const size_t vb = O_SC_V + (size_t)n * 192 + d * 3;
        out[vb]     = v0 * S640;
        out[vb + 1] = v1 * S640;
        out[vb + 2] = aV2[jj] * S640;
        g_xs[(size_t)n * 64 + d] = accS2[jj] * 0.125f;
        float s0, s1; upk2(aV01s[jj], s0, s1);
        g_xv4[(size_t)n * 64 + d] =
            make_float4(s0 * 0.125f, s1 * 0.125f, aV2s[jj] * 0.125f, 0.f);
    }
}

// ============================================================================
// K2: edge MLP, thread-per-edge, all weights in smem, f32x2 + LDS.128
// ============================================================================
__global__ __launch_bounds__(256, 1) void k_mlp(
    const float* __restrict__ feats,
    const float* __restrict__ W0, const float* __restrict__ W1,
    const float* __restrict__ W2, const float* __restrict__ W3)
{
    extern __shared__ float sw[];
    float* sW0 = sw;             // 8x64
    float* sW1 = sw + 512;       // 64x64
    float* sW2 = sw + 4608;      // 64x64
    float* sW3 = sw + 8704;      // 64x320
    float* sH  = sw + 29184;     // 256 x 65

    const int t = threadIdx.x;
    for (int i = t; i < 512;   i += 256) sW0[i] = W0[i];
    for (int i = t; i < 4096;  i += 256) { sW1[i] = W1[i]; sW2[i] = W2[i]; }
    for (int i = t; i < 20480; i += 256) sW3[i] = W3[i];
    __syncthreads();

    const int e = blockIdx.x * 256 + t;
    float* h = sH + t * 65;

    const float4 fa = *(const float4*)(feats + (size_t)e * 8);
    const float4 fb = *(const float4*)(feats + (size_t)e * 8 + 4);
    const float f[8] = {fa.x, fa.y, fa.z, fa.w, fb.x, fb.y, fb.z, fb.w};

    ull acc[32];

    // layer 0
#pragma unroll
    for (int dp = 0; dp < 32; dp++) acc[dp] = 0ull;
#pragma unroll
    for (int c = 0; c < 8; c++) {
        const ull a2 = pk2(f[c], f[c]);
        const ulonglong2* w = (const ulonglong2*)(sW0 + c * 64);
#pragma unroll
        for (int q = 0; q < 16; q++) {
            const ulonglong2 ww = w[q];
            acc[2 * q]     = ff2(a2, ww.x, acc[2 * q]);
            acc[2 * q + 1] = ff2(a2, ww.y, acc[2 * q + 1]);
        }
    }
#pragma unroll
    for (int dp = 0; dp < 32; dp++) {
        float lo, hi; upk2(acc[dp], lo, hi);
        h[2 * dp]     = silu_f(lo * 0.3535533905932738f);
        h[2 * dp + 1] = silu_f(hi * 0.3535533905932738f);
    }

    // layers 1, 2
    for (int L = 0; L < 2; L++) {
        const float* W = L ? sW2 : sW1;
#pragma unroll
        for (int dp = 0; dp < 32; dp++) acc[dp] = 0ull;
        for (int c = 0; c < 64; c++) {
            const float hc = h[c];
            const ull a2 = pk2(hc, hc);
            const ulonglong2* w = (const ulonglong2*)(W + c * 64);
#pragma unroll
            for (int q = 0; q < 16; q++) {
                const ulonglong2 ww = w[q];
                acc[2 * q]     = ff2(a2, ww.x, acc[2 * q]);
                acc[2 * q + 1] = ff2(a2, ww.y, acc[2 * q + 1]);
            }
        }
#pragma unroll
        for (int dp = 0; dp < 32; dp++) {
            float lo, hi; upk2(acc[dp], lo, hi);
            h[2 * dp]     = silu_f(lo * 0.125f);
            h[2 * dp + 1] = silu_f(hi * 0.125f);
        }
    }

    // layer 3: 5 chunks of 64 outputs
    float* outp = g_tpw + (size_t)e * 320;
    for (int ch = 0; ch < 5; ch++) {
#pragma unroll
        for (int dp = 0; dp < 32; dp++) acc[dp] = 0ull;
        for (int c = 0; c < 64; c++) {
            const float hc = h[c];
            const ull a2 = pk2(hc, hc);
            const ulonglong2* w = (const ulonglong2*)(sW3 + c * 320 + ch * 64);
#pragma unroll
            for (int q = 0; q < 16; q++) {
                const ulonglong2 ww = w[q];
                acc[2 * q]     = ff2(a2, ww.x, acc[2 * q]);
                acc[2 * q + 1] = ff2(a2, ww.y, acc[2 * q + 1]);
            }
        }
#pragma unroll
        for (int q = 0; q < 16; q++) {
            float l0, h0, l1, h1;
            upk2(acc[2 * q], l0, h0);
            upk2(acc[2 * q + 1], l1, h1);
            *(float4*)(outp + ch * 64 + 4 * q) =
                make_float4(l0 * 0.125f, h0 * 0.125f, l1 * 0.125f, h1 * 0.125f);
        }
    }
}

// ============================================================================
// CSR build
// ============================================================================
__global__ void k_zero() {
    const int i = blockIdx.x * blockDim.x + threadIdx.x;
    if (i < NN) g_cnt[i] = 0;
}
__global__ void k_count(const int* __restrict__ recv) {
    const int e = blockIdx.x * blockDim.x + threadIdx.x;
    if (e < EE) atomicAdd(&g_cnt[recv[e]], 1);
}
__global__ void k_scan() {
    __shared__ int ss[1024];
    const int t = threadIdx.x;
    const int base = t * 32;
    int loc[32];
    int s = 0;
#pragma unroll
    for (int i = 0; i < 32; i++) { loc[i] = s; s += g_cnt[base + i]; }
    ss[t] = s;
    __syncthreads();
    for (int dd = 1; dd < 1024; dd <<= 1) {
        const int v = (t >= dd) ? ss[t - dd] : 0;
        __syncthreads();
        ss[t] += v;
        __syncthreads();
    }
    const int pre = (t > 0) ? ss[t - 1] : 0;
#pragma unroll
    for (int i = 0; i < 32; i++) {
        g_off[base + i] = pre + loc[i];
        g_woff[base + i] = 0;
    }
    if (t == 1023) g_off[NN] = pre + s;
}
__global__ void k_fill(const int* __restrict__ recv) {
    const int e = blockIdx.x * blockDim.x + threadIdx.x;
    if (e < EE) {
        const int r = recv[e];
        const int p = atomicAdd(&g_woff[r], 1);
        g_eord[g_off[r] + p] = e;
    }
}
__global__ void k_sort() {
    const int n = blockIdx.x * blockDim.x + threadIdx.x;
    if (n >= NN) return;
    const int s = g_off[n], e = g_off[n + 1];
    for (int i = s + 1; i < e; i++) {
        const int v = g_eord[i];
        int j = i - 1;
        while (j >= s && g_eord[j] > v) { g_eord[j + 1] = g_eord[j]; j--; }
        g_eord[j + 1] = v;
    }
}

// ============================================================================
// K4: gather-side aggregation + fused output GEMMs
// 4 nodes/block, 64 threads/node
// ============================================================================
__global__ __launch_bounds__(256) void k_agg(
    const int* __restrict__ send, const float* __restrict__ eattr,
    const float* __restrict__ Wms, const float* __restrict__ Wmv,
    float* __restrict__ out)
{
    __shared__ float sms[4][128];
    __shared__ ull   smv[4][192][2];   // [0]=(v0,v1), [1]=(v2, -)
    const int t = threadIdx.x;
    const int g = t >> 6, c = t & 63;
    const int n = blockIdx.x * 4 + g;
    const int e0 = g_off[n], e1 = g_off[n + 1];

    float as0 = 0.f, as1 = 0.f;
    ull   av0_01 = 0ull, av1_01 = 0ull, av2_01 = 0ull;
    float av0_2 = 0.f, av1_2 = 0.f, av2_2 = 0.f;

    for (int p = e0; p < e1; p++) {
        const int e = g_eord[p];
        const int s = __ldg(send + e);
        const float4 ea = __ldg((const float4*)eattr + e);
        const float sh0 = ea.x, s1x = ea.y, s1y = ea.z, s1z = ea.w;
        const float* tp = g_tpw + (size_t)e * 320 + c;
        const float w0 = tp[0], w1 = tp[64], w2 = tp[128], w3 = tp[192], w4 = tp[256];
        const float xs = __ldg(g_xs + (size_t)s * 64 + c);
        const float4 xv = __ldg(g_xv4 + (size_t)s * 64 + c);

        as0 = fmaf(w0 * xs, sh0, as0);
        const float dt = xv.x * s1x + xv.y * s1y + xv.z * s1z;
        as1 = fmaf(w3, dt, as1);

        const float t1 = w1 * xs;
        av0_01 = ff2(pk2(t1, t1), pk2(s1x, s1y), av0_01);
        av0_2  = fmaf(t1, s1z, av0_2);

        const ull w2sh = pk2(w2 * sh0, w2 * sh0);
        av1_01 = ff2(pk2(xv.x, xv.y), w2sh, av1_01);
        av1_2  = fmaf(w2 * xv.z, sh0, av1_2);

        const float cx = xv.y * s1z - xv.z * s1y;
        const float cy = xv.z * s1x - xv.x * s1z;
        const float cz = xv.x * s1y - xv.y * s1x;
        av2_01 = ff2(pk2(cx, cy), pk2(w4, w4), av2_01);
        av2_2  = fmaf(w4, cz, av2_2);
    }

    const float INV  = 0.3535533905932738f;            // 1/sqrt(8)
    const float INV3 = INV * 0.5773502691896258f;
    const float INV2 = INV * 0.7071067811865476f;
    sms[g][c]      = as0 * INV;
    sms[g][64 + c] = as1 * INV3;
    {
        float a, b;
        upk2(av0_01, a, b);
        smv[g][c][0]       = pk2(a * INV, b * INV);
        smv[g][c][1]       = pk2(av0_2 * INV, 0.f);
        upk2(av1_01, a, b);
        smv[g][64 + c][0]  = pk2(a * INV, b * INV);
        smv[g][64 + c][1]  = pk2(av1_2 * INV, 0.f);
        upk2(av2_01, a, b);
        smv[g][128 + c][0] = pk2(a * INV2, b * INV2);
        smv[g][128 + c][1] = pk2(av2_2 * INV2, 0.f);
    }
    __syncthreads();

    const int d = c;
    float o = 0.f;
    for (int k = 0; k < 128; k++)
        o = fmaf(sms[g][k], __ldg(Wms + k * 64 + d), o);
    out[(size_t)n * 64 + d] = o * 0.08838834764831845f;   // 1/sqrt(128)

    ull ov01 = 0ull;
    float ov2 = 0.f;
    for (int k = 0; k < 192; k++) {
        const float w = __ldg(Wmv + k * 64 + d);
        const ull wd = pk2(w, w);
        ov01 = ff2(smv[g][k][0], wd, ov01);
        float m2, junk; upk2(smv[g][k][1], m2, junk);
        ov2 = fmaf(m2, w, ov2);
    }
    float o0, o1; upk2(ov01, o0, o1);
    const size_t ob = O_OUT_V + (size_t)n * 192 + d * 3;
    const float S192 = 0.07216878364870323f;              // 1/sqrt(192)
    out[ob]     = o0 * S192;
    out[ob + 1] = o1 * S192;
    out[ob + 2] = ov2 * S192;
}

// ============================================================================
extern "C" void kernel_launch(void* const* d_in, const int* in_sizes, int n_in,
                              void* d_out, int out_size)
{
    const float* node_attrs = (const float*)d_in[0];
    const float* x_s        = (const float*)d_in[1];
    const float* x_v        = (const float*)d_in[2];
    const float* edge_attrs = (const float*)d_in[3];
    const float* edge_feats = (const float*)d_in[4];
    const int*   senders    = (const int*)d_in[5];
    const int*   receivers  = (const int*)d_in[6];
    const float* W_sc_s     = (const float*)d_in[7];
    const float* W_sc_v     = (const float*)d_in[8];
    const float* W_self_s   = (const float*)d_in[9];
    const float* W_self_v   = (const float*)d_in[10];
    const float* mlp_W0     = (const float*)d_in[11];
    const float* mlp_W1     = (const float*)d_in[12];
    const float* mlp_W2     = (const float*)d_in[13];
    const float* mlp_W3     = (const float*)d_in[14];
    const float* W_msg_s    = (const float*)d_in[15];
    const float* W_msg_v    = (const float*)d_in[16];
    float* out = (float*)d_out;

    const size_t mlp_smem = (size_t)(29184 + 256 * 65) * sizeof(float);
    cudaFuncSetAttribute(k_mlp, cudaFuncAttributeMaxDynamicSharedMemorySize,
                         (int)mlp_smem);

    k_prep<<<160, 256>>>(W_sc_s, W_sc_v, W_self_s, W_self_v);
    k_zero<<<NN / 256, 256>>>();
    k_count<<<EE / 256, 256>>>(receivers);
    k_scan<<<1, 1024>>>();
    k_fill<<<EE / 256, 256>>>(receivers);
    k_mlp<<<EE / 256, 256, mlp_smem>>>(edge_feats, mlp_W0, mlp_W1, mlp_W2, mlp_W3);
    k_sort<<<NN / 128, 128>>>();
    k_node<<<NN / 16, 256>>>(node_attrs, x_s, x_v, out);
    k_agg<<<NN / 4, 256>>>(senders, edge_attrs, W_msg_s, W_msg_v, out);
}